// round 15
// baseline (speedup 1.0000x reference)
#include <cuda_runtime.h>
#include <stdint.h>
#include <math.h>

#define BATCH 256
#define N0 400
#define N1 200
#define N2 100
#define NT 50
#define NP 56      // col count for M / Y
#define LDA 51     // smem leading dim for Ts
#define LDB 52     // stride for fp32 Clenshaw buffers / Wsym
#define LDI 36     // stride (uints) for bf16 pair image
#define NFEAT 1275
#define CHEB_D 8   // Chebyshev degree for matrix log

#define NKCH 25    // K chunks of 16 in k_xmh

// dynamic smem layout for k_poly
#define OFF_TS 0
#define OFF_BA (NT * LDA)
#define OFF_BB (OFF_BA + NT * LDB)
#define OFF_IH (OFF_BB + NT * LDB)            // uint region
#define POLY_SMEM ((OFF_IH + 2 * 64 * LDI) * 4)

__device__ __align__(16) float g_M[N0 * NP];                 // W1@W2@W3 padded (400x56)
__device__ __align__(16) float g_Y[(size_t)BATCH * N0 * NP]; // X@M    (256x400x56)
__device__ __align__(16) float g_Wsym[7 * NT * LDB];         // symmetrized head weights
// B = M as k-pair-packed bf16 (hi / lo split), [n][200 pairs]
__device__ __align__(16) unsigned g_Bph[56 * 200];
__device__ __align__(16) unsigned g_Bpl[56 * 200];

// packed dual-fp32 FMA
__device__ __forceinline__ void ffma2(float2& d, float2 a, float2 b) {
    asm("fma.rn.f32x2 %0, %1, %2, %0;"
        : "+l"(*reinterpret_cast<unsigned long long*>(&d))
        : "l"(*reinterpret_cast<unsigned long long*>(&a)),
          "l"(*reinterpret_cast<unsigned long long*>(&b)));
}

// pack two f32 to bf16x2: low half <- a, high half <- b
__device__ __forceinline__ unsigned pack_bf16x2(float a, float b) {
    unsigned r;
    asm("cvt.rn.bf16x2.f32 %0, %1, %2;" : "=r"(r) : "f"(b), "f"(a));
    return r;
}

__device__ __forceinline__ void cp16(unsigned dst_smem, const void* src, int src_bytes) {
    asm volatile("cp.async.cg.shared.global [%0], [%1], 16, %2;"
                 :: "r"(dst_smem), "l"(src), "r"(src_bytes));
}
__device__ __forceinline__ void cp_commit() {
    asm volatile("cp.async.commit_group;");
}
template <int N>
__device__ __forceinline__ void cp_wait() {
    asm volatile("cp.async.wait_group %0;" :: "n"(N));
}

// HMMA bf16: D(16x8,f32) += A(16x16) * B(16x8)
__device__ __forceinline__ void mma16816(float* d, const unsigned* a, unsigned b0,
                                         unsigned b1) {
    asm("mma.sync.aligned.m16n8k16.row.col.f32.bf16.bf16.f32 "
        "{%0,%1,%2,%3}, {%4,%5,%6,%7}, {%8,%9}, {%0,%1,%2,%3};"
        : "+f"(d[0]), "+f"(d[1]), "+f"(d[2]), "+f"(d[3])
        : "r"(a[0]), "r"(a[1]), "r"(a[2]), "r"(a[3]), "r"(b0), "r"(b1));
}

// ---------------- prep1: M = W1 @ (W2 @ W3), T recomputed per block in smem ----------------
__global__ __launch_bounds__(256) void k_prep1(const float* __restrict__ W1,
                                               const float* __restrict__ W2,
                                               const float* __restrict__ W3) {
    __shared__ float sT[N1 * NT];  // 40 KB
    int tid = threadIdx.x;
    for (int t = tid; t < N1 * NT; t += 256) {
        int i = t / NT, j = t - (t / NT) * NT;
        float acc = 0.f;
        for (int k = 0; k < N2; k++) acc += W2[i * N2 + k] * W3[k * NT + j];
        sT[t] = acc;
    }
    __syncthreads();
    int per = (N0 * NP + gridDim.x - 1) / gridDim.x;
    int lo = blockIdx.x * per;
    int hi = lo + per;
    if (hi > N0 * NP) hi = N0 * NP;
    for (int t = lo + tid; t < hi; t += 256) {
        int i = t / NP, j = t - (t / NP) * NP;
        float acc = 0.f;
        if (j < NT) {
            for (int k = 0; k < N1; k++) acc += W1[i * N1 + k] * sT[k * NT + j];
        }
        g_M[t] = acc;
    }
}

// ---------------- prep2: bpk (blocks 0..43) + wsym (blocks 44..115) ----------------
__global__ void k_prep2(const float* __restrict__ Wl) {
    int bid = blockIdx.x;
    int tid = threadIdx.x;
    if (bid < 44) {
        int t = bid * 256 + tid;
        if (t >= 56 * 200) return;
        int n = t / 200, p = t - (t / 200) * 200;
        float m0 = g_M[(2 * p) * NP + n];
        float m1 = g_M[(2 * p + 1) * NP + n];
        unsigned h = pack_bf16x2(m0, m1);
        float f0 = __uint_as_float(h << 16);
        float f1 = __uint_as_float(h & 0xFFFF0000u);
        unsigned l = pack_bf16x2(m0 - f0, m1 - f1);
        g_Bph[n * 200 + p] = h;
        g_Bpl[n * 200 + p] = l;
    } else {
        int t = (bid - 44) * 256 + tid;
        if (t >= 7 * NT * LDB) return;
        int c = t / (NT * LDB), l = t - c * (NT * LDB);
        int i = l / LDB, j = l - i * LDB;
        float v = 0.f;
        if (j < NT) {
            int lo = i < j ? i : j, hi = i < j ? j : i;
            int ti = lo * (101 - lo) / 2 + (hi - lo);
            float w = Wl[c * NFEAT + ti];
            v = (i == j) ? w : w * 0.70710678118654752f;
        }
        g_Wsym[t] = v;
    }
}

// ---------------- K2: Y[b] = X[b] @ M via HMMA bf16 split (unchanged from r14) ----------------
__global__ __launch_bounds__(256) void k_xmh(const float* __restrict__ X) {
    __shared__ __align__(16) unsigned sBh[2][672];
    __shared__ __align__(16) unsigned sBl[2][672];
    int tid = threadIdx.x;
    int wid = tid >> 5, lane = tid & 31;
    int gid = lane >> 2, tig = lane & 3;
    int b = blockIdx.y;
    int r0 = blockIdx.x * 128 + wid * 16 + gid;
    int r1 = r0 + 8;
    const float* Xb = X + (size_t)b * N0 * N0;
    float* Yb = g_Y + (size_t)b * N0 * NP;

    unsigned sbh = (unsigned)__cvta_generic_to_shared(&sBh[0][0]);
    unsigned sbl = (unsigned)__cvta_generic_to_shared(&sBl[0][0]);

    float d[7][4];
#pragma unroll
    for (int t = 0; t < 7; t++)
#pragma unroll
        for (int e = 0; e < 4; e++) d[t][e] = 0.f;

    auto stageB = [&](int c, int buf) {
        if (tid < 224) {
            int n = tid >> 2, q = tid & 3;
            int e = q & 1;
            const unsigned* src = ((q >> 1) ? g_Bpl : g_Bph) + n * 200 + c * 8 + e * 4;
            unsigned base = (q >> 1) ? sbl : sbh;
            cp16(base + (unsigned)((buf * 672 + n * 12 + e * 4) * 4), src, 16);
        }
        cp_commit();
    };
    auto loadA = [&](float2* xa, int c) {
        int k0 = c * 16 + 2 * tig;
        float2 z = make_float2(0.f, 0.f);
        xa[0] = xa[1] = xa[2] = xa[3] = z;
        if (r0 < N0) {
            xa[0] = *(const float2*)(Xb + (size_t)r0 * N0 + k0);
            xa[2] = *(const float2*)(Xb + (size_t)r0 * N0 + k0 + 8);
        }
        if (r1 < N0) {
            xa[1] = *(const float2*)(Xb + (size_t)r1 * N0 + k0);
            xa[3] = *(const float2*)(Xb + (size_t)r1 * N0 + k0 + 8);
        }
    };

    float2 xn[4];
    stageB(0, 0);
    loadA(xn, 0);
    for (int c = 0; c < NKCH; c++) {
        int buf = c & 1;
        if (c + 1 < NKCH) {
            stageB(c + 1, buf ^ 1);
            cp_wait<1>();
        } else {
            cp_wait<0>();
        }
        __syncthreads();
        float2 xa[4];
#pragma unroll
        for (int e = 0; e < 4; e++) xa[e] = xn[e];
        if (c + 1 < NKCH) loadA(xn, c + 1);
        unsigned ah[4], al[4];
#pragma unroll
        for (int e = 0; e < 4; e++) {
            ah[e] = pack_bf16x2(xa[e].x, xa[e].y);
            float f0 = __uint_as_float(ah[e] << 16);
            float f1 = __uint_as_float(ah[e] & 0xFFFF0000u);
            al[e] = pack_bf16x2(xa[e].x - f0, xa[e].y - f1);
        }
#pragma unroll
        for (int t = 0; t < 7; t++) {
            int nb = (t * 8 + gid) * 12;
            unsigned bh0 = sBh[buf][nb + tig];
            unsigned bh1 = sBh[buf][nb + 4 + tig];
            unsigned bl0 = sBl[buf][nb + tig];
            unsigned bl1 = sBl[buf][nb + 4 + tig];
            mma16816(d[t], ah, bh0, bh1);
            mma16816(d[t], al, bh0, bh1);
            mma16816(d[t], ah, bl0, bl1);
        }
        __syncthreads();
    }
#pragma unroll
    for (int t = 0; t < 7; t++) {
        int col = t * 8 + 2 * tig;
        if (r0 < N0) *(float2*)(Yb + (size_t)r0 * NP + col) = make_float2(d[t][0], d[t][1]);
        if (r1 < N0) *(float2*)(Yb + (size_t)r1 * NP + col) = make_float2(d[t][2], d[t][3]);
    }
}

// ---------------- K3: h = M^T Y (f32x2), log via HMMA Clenshaw, head ----------------
__global__ __launch_bounds__(256) void k_poly(const float* __restrict__ bl,
                                              float* __restrict__ out) {
    extern __shared__ float dsm[];
    float* sTs = dsm + OFF_TS;
    float* bufA = dsm + OFF_BA;
    float* bufB = dsm + OFF_BB;
    unsigned* sIh = (unsigned*)(dsm + OFF_IH);
    unsigned* sIl = sIh + 64 * LDI;

    __shared__ float s_row[NT];
    __shared__ float s_bb;
    __shared__ float s_red[7 * 8];

    int b = blockIdx.x;
    int tid = threadIdx.x;
    int wid = tid >> 5, lane = tid & 31;
    int gid = lane >> 2, tig = lane & 3;
    int rs = wid >> 1, ch = wid & 1;
    const float* Yb = g_Y + (size_t)b * N0 * NP;

    // ---- h = M^T Y : 125 threads, 2x10 microtile f32x2, staging in bufA/bufB ----
    {
        int rg = tid / 5, cg = tid - (tid / 5) * 5;
        int i0 = 2 * rg, j0 = 10 * cg;
        float2 h0[5] = {}, h1[5] = {};
        for (int kc = 0; kc < N0; kc += NT) {
            for (int l = tid; l < NT * NT; l += 256) {
                int r = l / NT, c = l - (l / NT) * NT;
                bufA[r * LDB + c] = g_M[(kc + r) * NP + c];
                bufB[r * LDB + c] = Yb[(kc + r) * NP + c];
            }
            __syncthreads();
            if (tid < 125) {
#pragma unroll 5
                for (int kk = 0; kk < NT; kk++) {
                    float m0 = bufA[kk * LDB + i0], m1 = bufA[kk * LDB + i0 + 1];
                    float2 a0 = make_float2(m0, m0), a1 = make_float2(m1, m1);
#pragma unroll
                    for (int j = 0; j < 5; j++) {
                        float2 yv = *(float2*)&bufB[kk * LDB + j0 + 2 * j];
                        ffma2(h0[j], a0, yv);
                        ffma2(h1[j], a1, yv);
                    }
                }
            }
            __syncthreads();
        }
        if (tid < 125) {
#pragma unroll
            for (int j = 0; j < 5; j++) {
                sTs[i0 * LDA + j0 + 2 * j] = h0[j].x;
                sTs[i0 * LDA + j0 + 2 * j + 1] = h0[j].y;
                sTs[(i0 + 1) * LDA + j0 + 2 * j] = h1[j].x;
                sTs[(i0 + 1) * LDA + j0 + 2 * j + 1] = h1[j].y;
            }
        }
        __syncthreads();
    }

    // ---- Gershgorin bound ----
    if (tid < NT) {
        float s = 0.f;
        for (int j = 0; j < NT; j++) s += fabsf(sTs[tid * LDA + j]);
        s_row[tid] = s;
    }
    __syncthreads();
    if (tid == 0) {
        float mx = 0.f;
        for (int i = 0; i < NT; i++) mx = fmaxf(mx, s_row[i]);
        s_bb = mx;
    }
    __syncthreads();
    float aa = 0.95f, bb = s_bb;
    float mid = 0.5f * (aa + bb);
    float kap = (bb - aa) / (bb + aa);
    float z = (1.f - sqrtf(fmaxf(1.f - kap * kap, 0.f))) / kap;
    float c0 = logf(mid) - logf(1.f + z * z);

    // ---- Ts = (2h - (a+b)I)/(b-a) ----
    {
        float inv = 1.f / (bb - aa);
        for (int l = tid; l < NT * NT; l += 256) {
            int i = l / NT, j = l - (l / NT) * NT;
            sTs[i * LDA + j] = (2.f * sTs[i * LDA + j] - (i == j ? (aa + bb) : 0.f)) * inv;
        }
    }
    // zero Clenshaw fp32 buffers and images
    for (int l = tid; l < NT * LDB; l += 256) {
        bufA[l] = 0.f;
        bufB[l] = 0.f;
    }
    for (int l = tid; l < 64 * LDI; l += 256) {
        sIh[l] = 0u;
        sIl[l] = 0u;
    }
    __syncthreads();
    float cD = -2.f * __powf(z, (float)CHEB_D) / (float)CHEB_D;  // k=8 even -> negative
    if (tid < NT) bufA[tid * LDB + tid] = cD;
    __syncthreads();
    // build image of bufA (b_D)
    for (int t = tid; t < NT * 25; t += 256) {
        int n = t / 25, p = t - (t / 25) * 25;
        float f0 = bufA[(2 * p) * LDB + n];
        float f1 = bufA[(2 * p + 1) * LDB + n];
        unsigned h = pack_bf16x2(f0, f1);
        float q0 = __uint_as_float(h << 16), q1 = __uint_as_float(h & 0xFFFF0000u);
        sIh[n * LDI + p] = h;
        sIl[n * LDI + p] = pack_bf16x2(f0 - q0, f1 - q1);
    }
    // preload Ts A-fragments (loop-invariant), bf16 hi/lo split
    unsigned ahf[4][4], alf[4][4];
    {
        int ra0 = 16 * rs + gid, ra1 = ra0 + 8;
#pragma unroll
        for (int ks = 0; ks < 4; ks++) {
            int c0 = 16 * ks + 2 * tig;
#pragma unroll
            for (int e = 0; e < 4; e++) {
                int r = (e & 1) ? ra1 : ra0;
                int c = c0 + ((e >> 1) ? 8 : 0);
                float f0 = (r < NT && c < NT) ? sTs[r * LDA + c] : 0.f;
                float f1 = (r < NT && c + 1 < NT) ? sTs[r * LDA + c + 1] : 0.f;
                unsigned h = pack_bf16x2(f0, f1);
                float q0 = __uint_as_float(h << 16), q1 = __uint_as_float(h & 0xFFFF0000u);
                ahf[ks][e] = h;
                alf[ks][e] = pack_bf16x2(f0 - q0, f1 - q1);
            }
        }
    }
    __syncthreads();

    // ---- Clenshaw via HMMA: b_k = ck I + 2 Ts b_{k+1} - b_{k+2} ----
    float* bcur = bufA;  // imaged (b_{k+1})
    float* bold = bufB;  // b_{k+2}; new b_k written here in place
    for (int k = CHEB_D - 1; k >= 0; k--) {
        float ck, m2;
        if (k >= 1) {
            ck = 2.f * __powf(z, (float)k) / (float)k;
            if (!(k & 1)) ck = -ck;
            m2 = 2.f;
        } else {
            ck = c0;
            m2 = 1.f;
        }
#pragma unroll
        for (int tt = 0; tt < 4; tt++) {
            float d[4] = {0.f, 0.f, 0.f, 0.f};
            int n = 32 * ch + 8 * tt + gid;
#pragma unroll
            for (int ks = 0; ks < 4; ks++) {
                unsigned b0h = sIh[n * LDI + 8 * ks + tig];
                unsigned b1h = sIh[n * LDI + 8 * ks + 4 + tig];
                unsigned b0l = sIl[n * LDI + 8 * ks + tig];
                unsigned b1l = sIl[n * LDI + 8 * ks + 4 + tig];
                mma16816(d, ahf[ks], b0h, b1h);
                mma16816(d, alf[ks], b0h, b1h);
                mma16816(d, ahf[ks], b0l, b1l);
            }
            int c0w = 32 * ch + 8 * tt + 2 * tig;
            if (c0w < NT) {
                int r = 16 * rs + gid;
                if (r < NT) {
                    float v0 = m2 * d[0] - bold[r * LDB + c0w] + (r == c0w ? ck : 0.f);
                    float v1 = m2 * d[1] - bold[r * LDB + c0w + 1] + (r == c0w + 1 ? ck : 0.f);
                    *(float2*)&bold[r * LDB + c0w] = make_float2(v0, v1);
                }
                int r2 = 16 * rs + gid + 8;
                if (r2 < NT) {
                    float v0 = m2 * d[2] - bold[r2 * LDB + c0w] + (r2 == c0w ? ck : 0.f);
                    float v1 = m2 * d[3] - bold[r2 * LDB + c0w + 1] + (r2 == c0w + 1 ? ck : 0.f);
                    *(float2*)&bold[r2 * LDB + c0w] = make_float2(v0, v1);
                }
            }
        }
        {
            float* tmp = bcur; bcur = bold; bold = tmp;  // bcur = newest (b_k)
        }
        __syncthreads();
        if (k > 0) {
            for (int t = tid; t < NT * 25; t += 256) {
                int n = t / 25, p = t - (t / 25) * 25;
                float f0 = bcur[(2 * p) * LDB + n];
                float f1 = bcur[(2 * p + 1) * LDB + n];
                unsigned h = pack_bf16x2(f0, f1);
                float q0 = __uint_as_float(h << 16), q1 = __uint_as_float(h & 0xFFFF0000u);
                sIh[n * LDI + p] = h;
                sIl[n * LDI + p] = pack_bf16x2(f0 - q0, f1 - q1);
            }
            __syncthreads();
        }
    }
    float* S = bcur;

    // ---- head: out[c] = <S, Wsym_c> + bl[c] ----
    float po[7] = {0, 0, 0, 0, 0, 0, 0};
    for (int l = tid; l < NT * LDB; l += 256) {
        float s = S[l];
#pragma unroll
        for (int c = 0; c < 7; c++) po[c] += s * g_Wsym[c * (NT * LDB) + l];
    }
    int lane2 = tid & 31, warp = tid >> 5;
#pragma unroll
    for (int off = 16; off > 0; off >>= 1) {
#pragma unroll
        for (int c = 0; c < 7; c++) po[c] += __shfl_down_sync(0xffffffffu, po[c], off);
    }
    if (lane2 == 0) {
#pragma unroll
        for (int c = 0; c < 7; c++) s_red[c * 8 + warp] = po[c];
    }
    __syncthreads();
    if (tid < 7) {
        float sum = bl[tid];
#pragma unroll
        for (int w = 0; w < 8; w++) sum += s_red[tid * 8 + w];
        out[b * 7 + tid] = sum;
    }
}

extern "C" void kernel_launch(void* const* d_in, const int* in_sizes, int n_in,
                              void* d_out, int out_size) {
    const float* x  = (const float*)d_in[0];
    const float* W1 = (const float*)d_in[1];
    const float* W2 = (const float*)d_in[2];
    const float* W3 = (const float*)d_in[3];
    const float* Wl = (const float*)d_in[4];
    const float* bl = (const float*)d_in[5];
    float* out = (float*)d_out;

    static int smem_set = 0;
    if (!smem_set) {
        cudaFuncSetAttribute(k_poly, cudaFuncAttributeMaxDynamicSharedMemorySize,
                             POLY_SMEM);
        smem_set = 1;
    }

    k_prep1<<<60, 256>>>(W1, W2, W3);
    k_prep2<<<116, 256>>>(Wl);
    k_xmh<<<dim3(4, BATCH), 256>>>(x);
    k_poly<<<BATCH, 256, POLY_SMEM>>>(bl, out);
}

// round 16
// speedup vs baseline: 1.3291x; 1.3291x over previous
#include <cuda_runtime.h>
#include <stdint.h>
#include <math.h>

#define BATCH 256
#define N0 400
#define N1 200
#define N2 100
#define NT 50
#define NP 56      // col count for M / Y
#define LDA 51     // smem leading dim for Ts
#define LDB 52     // stride for fp32 Clenshaw buffers / Wsym
#define LDI 36     // stride (uints) for bf16 pair image
#define NFEAT 1275
#define CHEB_D 8   // Chebyshev degree for matrix log

#define NKCH 25    // K chunks of 16 in k_xmh

// dynamic smem layout for k_poly
#define OFF_TS 0
#define OFF_BA (NT * LDA)
#define OFF_BB (OFF_BA + NT * LDB)
#define OFF_IH (OFF_BB + NT * LDB)            // uint region
#define POLY_SMEM ((OFF_IH + 2 * 64 * LDI) * 4)

__device__ __align__(16) float g_T[N1 * NT];                 // W2@W3  (200x50)
__device__ __align__(16) float g_M[N0 * NP];                 // W1@W2@W3 padded (400x56)
__device__ __align__(16) float g_Y[(size_t)BATCH * N0 * NP]; // X@M    (256x400x56)
__device__ __align__(16) float g_Wsym[7 * NT * LDB];         // symmetrized head weights
// B = M as k-pair-packed bf16 (hi / lo split), [n][200 pairs]
__device__ __align__(16) unsigned g_Bph[56 * 200];
__device__ __align__(16) unsigned g_Bpl[56 * 200];

// packed dual-fp32 FMA
__device__ __forceinline__ void ffma2(float2& d, float2 a, float2 b) {
    asm("fma.rn.f32x2 %0, %1, %2, %0;"
        : "+l"(*reinterpret_cast<unsigned long long*>(&d))
        : "l"(*reinterpret_cast<unsigned long long*>(&a)),
          "l"(*reinterpret_cast<unsigned long long*>(&b)));
}

// pack two f32 to bf16x2: low half <- a, high half <- b
__device__ __forceinline__ unsigned pack_bf16x2(float a, float b) {
    unsigned r;
    asm("cvt.rn.bf16x2.f32 %0, %1, %2;" : "=r"(r) : "f"(b), "f"(a));
    return r;
}

__device__ __forceinline__ void cp16(unsigned dst_smem, const void* src, int src_bytes) {
    asm volatile("cp.async.cg.shared.global [%0], [%1], 16, %2;"
                 :: "r"(dst_smem), "l"(src), "r"(src_bytes));
}
__device__ __forceinline__ void cp_commit() {
    asm volatile("cp.async.commit_group;");
}
template <int N>
__device__ __forceinline__ void cp_wait() {
    asm volatile("cp.async.wait_group %0;" :: "n"(N));
}

// HMMA bf16: D(16x8,f32) += A(16x16) * B(16x8)
__device__ __forceinline__ void mma16816(float* d, const unsigned* a, unsigned b0,
                                         unsigned b1) {
    asm("mma.sync.aligned.m16n8k16.row.col.f32.bf16.bf16.f32 "
        "{%0,%1,%2,%3}, {%4,%5,%6,%7}, {%8,%9}, {%0,%1,%2,%3};"
        : "+f"(d[0]), "+f"(d[1]), "+f"(d[2]), "+f"(d[3])
        : "r"(a[0]), "r"(a[1]), "r"(a[2]), "r"(a[3]), "r"(b0), "r"(b1));
}

// ---------------- K1a: T = W2 @ W3 ----------------
__global__ void k_w2w3(const float* __restrict__ W2, const float* __restrict__ W3) {
    int stride = gridDim.x * blockDim.x;
    for (int t = blockIdx.x * blockDim.x + threadIdx.x; t < N1 * NT; t += stride) {
        int i = t / NT, j = t - (t / NT) * NT;
        float acc = 0.f;
        for (int k = 0; k < N2; k++) acc += W2[i * N2 + k] * W3[k * NT + j];
        g_T[t] = acc;
    }
}

// ---------------- K1b: M = W1 @ T (zero-padded to 56 cols) ----------------
__global__ void k_w1t(const float* __restrict__ W1) {
    int stride = gridDim.x * blockDim.x;
    for (int t = blockIdx.x * blockDim.x + threadIdx.x; t < N0 * NP; t += stride) {
        int i = t / NP, j = t - (t / NP) * NP;
        float acc = 0.f;
        if (j < NT) {
            for (int k = 0; k < N1; k++) acc += W1[i * N1 + k] * g_T[k * NT + j];
        }
        g_M[t] = acc;
    }
}

// ---------------- prep2: bpk (blocks 0..43) + wsym (blocks 44..115) ----------------
__global__ void k_prep2(const float* __restrict__ Wl) {
    int bid = blockIdx.x;
    int tid = threadIdx.x;
    if (bid < 44) {
        int t = bid * 256 + tid;
        if (t >= 56 * 200) return;
        int n = t / 200, p = t - (t / 200) * 200;
        float m0 = g_M[(2 * p) * NP + n];
        float m1 = g_M[(2 * p + 1) * NP + n];
        unsigned h = pack_bf16x2(m0, m1);
        float f0 = __uint_as_float(h << 16);
        float f1 = __uint_as_float(h & 0xFFFF0000u);
        unsigned l = pack_bf16x2(m0 - f0, m1 - f1);
        g_Bph[n * 200 + p] = h;
        g_Bpl[n * 200 + p] = l;
    } else {
        int t = (bid - 44) * 256 + tid;
        if (t >= 7 * NT * LDB) return;
        int c = t / (NT * LDB), l = t - c * (NT * LDB);
        int i = l / LDB, j = l - i * LDB;
        float v = 0.f;
        if (j < NT) {
            int lo = i < j ? i : j, hi = i < j ? j : i;
            int ti = lo * (101 - lo) / 2 + (hi - lo);
            float w = Wl[c * NFEAT + ti];
            v = (i == j) ? w : w * 0.70710678118654752f;
        }
        g_Wsym[t] = v;
    }
}

// ---------------- K2: Y[b] = X[b] @ M via HMMA bf16 split ----------------
__global__ __launch_bounds__(256) void k_xmh(const float* __restrict__ X) {
    __shared__ __align__(16) unsigned sBh[2][672];
    __shared__ __align__(16) unsigned sBl[2][672];
    int tid = threadIdx.x;
    int wid = tid >> 5, lane = tid & 31;
    int gid = lane >> 2, tig = lane & 3;
    int b = blockIdx.y;
    int r0 = blockIdx.x * 128 + wid * 16 + gid;
    int r1 = r0 + 8;
    const float* Xb = X + (size_t)b * N0 * N0;
    float* Yb = g_Y + (size_t)b * N0 * NP;

    unsigned sbh = (unsigned)__cvta_generic_to_shared(&sBh[0][0]);
    unsigned sbl = (unsigned)__cvta_generic_to_shared(&sBl[0][0]);

    float d[7][4];
#pragma unroll
    for (int t = 0; t < 7; t++)
#pragma unroll
        for (int e = 0; e < 4; e++) d[t][e] = 0.f;

    auto stageB = [&](int c, int buf) {
        if (tid < 224) {
            int n = tid >> 2, q = tid & 3;
            int e = q & 1;
            const unsigned* src = ((q >> 1) ? g_Bpl : g_Bph) + n * 200 + c * 8 + e * 4;
            unsigned base = (q >> 1) ? sbl : sbh;
            cp16(base + (unsigned)((buf * 672 + n * 12 + e * 4) * 4), src, 16);
        }
        cp_commit();
    };
    auto loadA = [&](float2* xa, int c) {
        int k0 = c * 16 + 2 * tig;
        float2 z = make_float2(0.f, 0.f);
        xa[0] = xa[1] = xa[2] = xa[3] = z;
        if (r0 < N0) {
            xa[0] = *(const float2*)(Xb + (size_t)r0 * N0 + k0);
            xa[2] = *(const float2*)(Xb + (size_t)r0 * N0 + k0 + 8);
        }
        if (r1 < N0) {
            xa[1] = *(const float2*)(Xb + (size_t)r1 * N0 + k0);
            xa[3] = *(const float2*)(Xb + (size_t)r1 * N0 + k0 + 8);
        }
    };

    float2 xn[4];
    stageB(0, 0);
    loadA(xn, 0);
    for (int c = 0; c < NKCH; c++) {
        int buf = c & 1;
        if (c + 1 < NKCH) {
            stageB(c + 1, buf ^ 1);
            cp_wait<1>();
        } else {
            cp_wait<0>();
        }
        __syncthreads();
        float2 xa[4];
#pragma unroll
        for (int e = 0; e < 4; e++) xa[e] = xn[e];
        if (c + 1 < NKCH) loadA(xn, c + 1);
        unsigned ah[4], al[4];
#pragma unroll
        for (int e = 0; e < 4; e++) {
            ah[e] = pack_bf16x2(xa[e].x, xa[e].y);
            float f0 = __uint_as_float(ah[e] << 16);
            float f1 = __uint_as_float(ah[e] & 0xFFFF0000u);
            al[e] = pack_bf16x2(xa[e].x - f0, xa[e].y - f1);
        }
#pragma unroll
        for (int t = 0; t < 7; t++) {
            int nb = (t * 8 + gid) * 12;
            unsigned bh0 = sBh[buf][nb + tig];
            unsigned bh1 = sBh[buf][nb + 4 + tig];
            unsigned bl0 = sBl[buf][nb + tig];
            unsigned bl1 = sBl[buf][nb + 4 + tig];
            mma16816(d[t], ah, bh0, bh1);
            mma16816(d[t], al, bh0, bh1);
            mma16816(d[t], ah, bl0, bl1);
        }
        __syncthreads();
    }
#pragma unroll
    for (int t = 0; t < 7; t++) {
        int col = t * 8 + 2 * tig;
        if (r0 < N0) *(float2*)(Yb + (size_t)r0 * NP + col) = make_float2(d[t][0], d[t][1]);
        if (r1 < N0) *(float2*)(Yb + (size_t)r1 * NP + col) = make_float2(d[t][2], d[t][3]);
    }
}

// ---------------- K3: h = M^T Y (f32x2), log via HMMA Clenshaw, head ----------------
__global__ __launch_bounds__(256) void k_poly(const float* __restrict__ bl,
                                              float* __restrict__ out) {
    extern __shared__ float dsm[];
    float* sTs = dsm + OFF_TS;
    float* bufA = dsm + OFF_BA;
    float* bufB = dsm + OFF_BB;
    unsigned* sIh = (unsigned*)(dsm + OFF_IH);
    unsigned* sIl = sIh + 64 * LDI;

    __shared__ float s_row[NT];
    __shared__ float s_bb;
    __shared__ float s_red[7 * 8];

    int b = blockIdx.x;
    int tid = threadIdx.x;
    int wid = tid >> 5, lane = tid & 31;
    int gid = lane >> 2, tig = lane & 3;
    int rs = wid >> 1, ch = wid & 1;
    const float* Yb = g_Y + (size_t)b * N0 * NP;

    // ---- h = M^T Y : 125 threads, 2x10 microtile f32x2, staging in bufA/bufB ----
    {
        int rg = tid / 5, cg = tid - (tid / 5) * 5;
        int i0 = 2 * rg, j0 = 10 * cg;
        float2 h0[5] = {}, h1[5] = {};
        for (int kc = 0; kc < N0; kc += NT) {
            for (int l = tid; l < NT * NT; l += 256) {
                int r = l / NT, c = l - (l / NT) * NT;
                bufA[r * LDB + c] = g_M[(kc + r) * NP + c];
                bufB[r * LDB + c] = Yb[(kc + r) * NP + c];
            }
            __syncthreads();
            if (tid < 125) {
#pragma unroll 5
                for (int kk = 0; kk < NT; kk++) {
                    float m0 = bufA[kk * LDB + i0], m1 = bufA[kk * LDB + i0 + 1];
                    float2 a0 = make_float2(m0, m0), a1 = make_float2(m1, m1);
#pragma unroll
                    for (int j = 0; j < 5; j++) {
                        float2 yv = *(float2*)&bufB[kk * LDB + j0 + 2 * j];
                        ffma2(h0[j], a0, yv);
                        ffma2(h1[j], a1, yv);
                    }
                }
            }
            __syncthreads();
        }
        if (tid < 125) {
#pragma unroll
            for (int j = 0; j < 5; j++) {
                sTs[i0 * LDA + j0 + 2 * j] = h0[j].x;
                sTs[i0 * LDA + j0 + 2 * j + 1] = h0[j].y;
                sTs[(i0 + 1) * LDA + j0 + 2 * j] = h1[j].x;
                sTs[(i0 + 1) * LDA + j0 + 2 * j + 1] = h1[j].y;
            }
        }
        __syncthreads();
    }

    // ---- Gershgorin bound ----
    if (tid < NT) {
        float s = 0.f;
        for (int j = 0; j < NT; j++) s += fabsf(sTs[tid * LDA + j]);
        s_row[tid] = s;
    }
    __syncthreads();
    if (tid == 0) {
        float mx = 0.f;
        for (int i = 0; i < NT; i++) mx = fmaxf(mx, s_row[i]);
        s_bb = mx;
    }
    __syncthreads();
    float aa = 0.95f, bb = s_bb;
    float mid = 0.5f * (aa + bb);
    float kap = (bb - aa) / (bb + aa);
    float z = (1.f - sqrtf(fmaxf(1.f - kap * kap, 0.f))) / kap;
    float c0 = logf(mid) - logf(1.f + z * z);

    // ---- Ts = (2h - (a+b)I)/(b-a) ----
    {
        float inv = 1.f / (bb - aa);
        for (int l = tid; l < NT * NT; l += 256) {
            int i = l / NT, j = l - (l / NT) * NT;
            sTs[i * LDA + j] = (2.f * sTs[i * LDA + j] - (i == j ? (aa + bb) : 0.f)) * inv;
        }
    }
    for (int l = tid; l < NT * LDB; l += 256) {
        bufA[l] = 0.f;
        bufB[l] = 0.f;
    }
    for (int l = tid; l < 64 * LDI; l += 256) {
        sIh[l] = 0u;
        sIl[l] = 0u;
    }
    __syncthreads();
    float cD = -2.f * __powf(z, (float)CHEB_D) / (float)CHEB_D;
    if (tid < NT) bufA[tid * LDB + tid] = cD;
    __syncthreads();
    for (int t = tid; t < NT * 25; t += 256) {
        int n = t / 25, p = t - (t / 25) * 25;
        float f0 = bufA[(2 * p) * LDB + n];
        float f1 = bufA[(2 * p + 1) * LDB + n];
        unsigned h = pack_bf16x2(f0, f1);
        float q0 = __uint_as_float(h << 16), q1 = __uint_as_float(h & 0xFFFF0000u);
        sIh[n * LDI + p] = h;
        sIl[n * LDI + p] = pack_bf16x2(f0 - q0, f1 - q1);
    }
    // preload Ts A-fragments (loop-invariant), bf16 hi/lo split
    unsigned ahf[4][4], alf[4][4];
    {
        int ra0 = 16 * rs + gid, ra1 = ra0 + 8;
#pragma unroll
        for (int ks = 0; ks < 4; ks++) {
            int c0 = 16 * ks + 2 * tig;
#pragma unroll
            for (int e = 0; e < 4; e++) {
                int r = (e & 1) ? ra1 : ra0;
                int c = c0 + ((e >> 1) ? 8 : 0);
                float f0 = (r < NT && c < NT) ? sTs[r * LDA + c] : 0.f;
                float f1 = (r < NT && c + 1 < NT) ? sTs[r * LDA + c + 1] : 0.f;
                unsigned h = pack_bf16x2(f0, f1);
                float q0 = __uint_as_float(h << 16), q1 = __uint_as_float(h & 0xFFFF0000u);
                ahf[ks][e] = h;
                alf[ks][e] = pack_bf16x2(f0 - q0, f1 - q1);
            }
        }
    }
    __syncthreads();

    // ---- Clenshaw via HMMA: b_k = ck I + 2 Ts b_{k+1} - b_{k+2} ----
    float* bcur = bufA;
    float* bold = bufB;
    for (int k = CHEB_D - 1; k >= 0; k--) {
        float ck, m2;
        if (k >= 1) {
            ck = 2.f * __powf(z, (float)k) / (float)k;
            if (!(k & 1)) ck = -ck;
            m2 = 2.f;
        } else {
            ck = c0;
            m2 = 1.f;
        }
#pragma unroll
        for (int tt = 0; tt < 4; tt++) {
            float d[4] = {0.f, 0.f, 0.f, 0.f};
            int n = 32 * ch + 8 * tt + gid;
#pragma unroll
            for (int ks = 0; ks < 4; ks++) {
                unsigned b0h = sIh[n * LDI + 8 * ks + tig];
                unsigned b1h = sIh[n * LDI + 8 * ks + 4 + tig];
                unsigned b0l = sIl[n * LDI + 8 * ks + tig];
                unsigned b1l = sIl[n * LDI + 8 * ks + 4 + tig];
                mma16816(d, ahf[ks], b0h, b1h);
                mma16816(d, alf[ks], b0h, b1h);
                mma16816(d, ahf[ks], b0l, b1l);
            }
            int c0w = 32 * ch + 8 * tt + 2 * tig;
            if (c0w < NT) {
                int r = 16 * rs + gid;
                if (r < NT) {
                    float v0 = m2 * d[0] - bold[r * LDB + c0w] + (r == c0w ? ck : 0.f);
                    float v1 = m2 * d[1] - bold[r * LDB + c0w + 1] + (r == c0w + 1 ? ck : 0.f);
                    *(float2*)&bold[r * LDB + c0w] = make_float2(v0, v1);
                }
                int r2 = 16 * rs + gid + 8;
                if (r2 < NT) {
                    float v0 = m2 * d[2] - bold[r2 * LDB + c0w] + (r2 == c0w ? ck : 0.f);
                    float v1 = m2 * d[3] - bold[r2 * LDB + c0w + 1] + (r2 == c0w + 1 ? ck : 0.f);
                    *(float2*)&bold[r2 * LDB + c0w] = make_float2(v0, v1);
                }
            }
        }
        {
            float* tmp = bcur; bcur = bold; bold = tmp;
        }
        __syncthreads();
        if (k > 0) {
            for (int t = tid; t < NT * 25; t += 256) {
                int n = t / 25, p = t - (t / 25) * 25;
                float f0 = bcur[(2 * p) * LDB + n];
                float f1 = bcur[(2 * p + 1) * LDB + n];
                unsigned h = pack_bf16x2(f0, f1);
                float q0 = __uint_as_float(h << 16), q1 = __uint_as_float(h & 0xFFFF0000u);
                sIh[n * LDI + p] = h;
                sIl[n * LDI + p] = pack_bf16x2(f0 - q0, f1 - q1);
            }
            __syncthreads();
        }
    }
    float* S = bcur;

    // ---- head: out[c] = <S, Wsym_c> + bl[c] ----
    float po[7] = {0, 0, 0, 0, 0, 0, 0};
    for (int l = tid; l < NT * LDB; l += 256) {
        float s = S[l];
#pragma unroll
        for (int c = 0; c < 7; c++) po[c] += s * g_Wsym[c * (NT * LDB) + l];
    }
    int lane2 = tid & 31, warp = tid >> 5;
#pragma unroll
    for (int off = 16; off > 0; off >>= 1) {
#pragma unroll
        for (int c = 0; c < 7; c++) po[c] += __shfl_down_sync(0xffffffffu, po[c], off);
    }
    if (lane2 == 0) {
#pragma unroll
        for (int c = 0; c < 7; c++) s_red[c * 8 + warp] = po[c];
    }
    __syncthreads();
    if (tid < 7) {
        float sum = bl[tid];
#pragma unroll
        for (int w = 0; w < 8; w++) sum += s_red[tid * 8 + w];
        out[b * 7 + tid] = sum;
    }
}

extern "C" void kernel_launch(void* const* d_in, const int* in_sizes, int n_in,
                              void* d_out, int out_size) {
    const float* x  = (const float*)d_in[0];
    const float* W1 = (const float*)d_in[1];
    const float* W2 = (const float*)d_in[2];
    const float* W3 = (const float*)d_in[3];
    const float* Wl = (const float*)d_in[4];
    const float* bl = (const float*)d_in[5];
    float* out = (float*)d_out;

    static int smem_set = 0;
    if (!smem_set) {
        cudaFuncSetAttribute(k_poly, cudaFuncAttributeMaxDynamicSharedMemorySize,
                             POLY_SMEM);
        smem_set = 1;
    }

    k_w2w3<<<40, 256>>>(W2, W3);
    k_w1t<<<88, 256>>>(W1);
    k_prep2<<<116, 256>>>(Wl);
    k_xmh<<<dim3(4, BATCH), 256>>>(x);
    k_poly<<<BATCH, 256, POLY_SMEM>>>(bl, out);
}

// round 17
// speedup vs baseline: 1.5247x; 1.1471x over previous
#include <cuda_runtime.h>
#include <stdint.h>
#include <math.h>

#define BATCH 256
#define N0 400
#define N1 200
#define N2 100
#define NT 50
#define NP 56      // col count for M / Y
#define LDA 51     // smem leading dim for Ts
#define LDB 52     // stride for fp32 Clenshaw buffers / Wsym
#define LDI 36     // stride (uints) for bf16 pair image
#define NFEAT 1275
#define CHEB_D 8   // Chebyshev degree for matrix log

#define BSTR 204   // uint stride for resident B in k_xmh (12n+p mod 32 conflict-free)
#define XMH_SMEM (2 * 56 * BSTR * 4)

// dynamic smem layout for k_poly
#define OFF_TS 0
#define OFF_BA (NT * LDA)
#define OFF_BB (OFF_BA + NT * LDB)
#define OFF_IH (OFF_BB + NT * LDB)            // uint region
#define POLY_SMEM ((OFF_IH + 2 * 64 * LDI) * 4)

__device__ __align__(16) float g_T[N1 * NT];                 // W2@W3  (200x50)
__device__ __align__(16) float g_M[N0 * NP];                 // W1@W2@W3 padded (400x56)
__device__ __align__(16) float g_Y[(size_t)BATCH * N0 * NP]; // X@M    (256x400x56)
__device__ __align__(16) float g_Wsym[7 * NT * LDB];         // symmetrized head weights
// B = M as k-pair-packed bf16 (hi / lo split), [n][200 pairs]
__device__ __align__(16) unsigned g_Bph[56 * 200];
__device__ __align__(16) unsigned g_Bpl[56 * 200];

// packed dual-fp32 FMA
__device__ __forceinline__ void ffma2(float2& d, float2 a, float2 b) {
    asm("fma.rn.f32x2 %0, %1, %2, %0;"
        : "+l"(*reinterpret_cast<unsigned long long*>(&d))
        : "l"(*reinterpret_cast<unsigned long long*>(&a)),
          "l"(*reinterpret_cast<unsigned long long*>(&b)));
}

// pack two f32 to bf16x2: low half <- a, high half <- b
__device__ __forceinline__ unsigned pack_bf16x2(float a, float b) {
    unsigned r;
    asm("cvt.rn.bf16x2.f32 %0, %1, %2;" : "=r"(r) : "f"(b), "f"(a));
    return r;
}

__device__ __forceinline__ void cp16(unsigned dst_smem, const void* src, int src_bytes) {
    asm volatile("cp.async.cg.shared.global [%0], [%1], 16, %2;"
                 :: "r"(dst_smem), "l"(src), "r"(src_bytes));
}
__device__ __forceinline__ void cp_commit() {
    asm volatile("cp.async.commit_group;");
}
template <int N>
__device__ __forceinline__ void cp_wait() {
    asm volatile("cp.async.wait_group %0;" :: "n"(N));
}

// HMMA bf16: D(16x8,f32) += A(16x16) * B(16x8)
__device__ __forceinline__ void mma16816(float* d, const unsigned* a, unsigned b0,
                                         unsigned b1) {
    asm("mma.sync.aligned.m16n8k16.row.col.f32.bf16.bf16.f32 "
        "{%0,%1,%2,%3}, {%4,%5,%6,%7}, {%8,%9}, {%0,%1,%2,%3};"
        : "+f"(d[0]), "+f"(d[1]), "+f"(d[2]), "+f"(d[3])
        : "r"(a[0]), "r"(a[1]), "r"(a[2]), "r"(a[3]), "r"(b0), "r"(b1));
}

// ---------------- K1a: T = W2 @ W3 ----------------
__global__ void k_w2w3(const float* __restrict__ W2, const float* __restrict__ W3) {
    int stride = gridDim.x * blockDim.x;
    for (int t = blockIdx.x * blockDim.x + threadIdx.x; t < N1 * NT; t += stride) {
        int i = t / NT, j = t - (t / NT) * NT;
        float acc = 0.f;
        for (int k = 0; k < N2; k++) acc += W2[i * N2 + k] * W3[k * NT + j];
        g_T[t] = acc;
    }
}

// ---------------- K1b: M = W1 @ T (zero-padded to 56 cols) ----------------
__global__ void k_w1t(const float* __restrict__ W1) {
    int stride = gridDim.x * blockDim.x;
    for (int t = blockIdx.x * blockDim.x + threadIdx.x; t < N0 * NP; t += stride) {
        int i = t / NP, j = t - (t / NP) * NP;
        float acc = 0.f;
        if (j < NT) {
            for (int k = 0; k < N1; k++) acc += W1[i * N1 + k] * g_T[k * NT + j];
        }
        g_M[t] = acc;
    }
}

// ---------------- prep2: bpk (blocks 0..43) + wsym (blocks 44..115) ----------------
__global__ void k_prep2(const float* __restrict__ Wl) {
    int bid = blockIdx.x;
    int tid = threadIdx.x;
    if (bid < 44) {
        int t = bid * 256 + tid;
        if (t >= 56 * 200) return;
        int n = t / 200, p = t - (t / 200) * 200;
        float m0 = g_M[(2 * p) * NP + n];
        float m1 = g_M[(2 * p + 1) * NP + n];
        unsigned h = pack_bf16x2(m0, m1);
        float f0 = __uint_as_float(h << 16);
        float f1 = __uint_as_float(h & 0xFFFF0000u);
        unsigned l = pack_bf16x2(m0 - f0, m1 - f1);
        g_Bph[n * 200 + p] = h;
        g_Bpl[n * 200 + p] = l;
    } else {
        int t = (bid - 44) * 256 + tid;
        if (t >= 7 * NT * LDB) return;
        int c = t / (NT * LDB), l = t - c * (NT * LDB);
        int i = l / LDB, j = l - i * LDB;
        float v = 0.f;
        if (j < NT) {
            int lo = i < j ? i : j, hi = i < j ? j : i;
            int ti = lo * (101 - lo) / 2 + (hi - lo);
            float w = Wl[c * NFEAT + ti];
            v = (i == j) ? w : w * 0.70710678118654752f;
        }
        g_Wsym[t] = v;
    }
}

// ---------------- K2: Y[b] = X[b] @ M via HMMA bf16 split ----------------
// B resident in smem (91KB, loaded once). 400 blocks x 16 warps; warp w handles
// global warp-tile wt = bid*16+w -> (batch wt/25, 16-row tile wt%25). No barriers
// in the K loop; warps fully decoupled.
__global__ __launch_bounds__(512, 2) void k_xmh(const float* __restrict__ X) {
    extern __shared__ __align__(16) unsigned sB[];
    unsigned* sBh = sB;
    unsigned* sBl = sB + 56 * BSTR;
    int tid = threadIdx.x;
    int wid = tid >> 5, lane = tid & 31;
    int gid = lane >> 2, tig = lane & 3;

    // ---- load all of B (hi+lo) into smem, once ----
    {
        unsigned sb = (unsigned)__cvta_generic_to_shared(sB);
        for (int t = tid; t < 2800; t += 512) {
            int n = t / 50, q = t - (t / 50) * 50;
            cp16(sb + (unsigned)((n * BSTR + q * 4) * 4), g_Bph + n * 200 + q * 4, 16);
        }
        for (int t = tid; t < 2800; t += 512) {
            int n = t / 50, q = t - (t / 50) * 50;
            cp16(sb + (unsigned)((56 * BSTR + n * BSTR + q * 4) * 4),
                 g_Bpl + n * 200 + q * 4, 16);
        }
        cp_commit();
        cp_wait<0>();
        __syncthreads();
    }

    int wt = blockIdx.x * 16 + wid;
    int b = wt / 25, rt = wt - b * 25;
    const float* Xb = X + (size_t)b * N0 * N0;
    float* Yb = g_Y + (size_t)b * N0 * NP;
    int r0 = rt * 16 + gid;
    int r1 = r0 + 8;

    float d[7][4];
#pragma unroll
    for (int t = 0; t < 7; t++)
#pragma unroll
        for (int e = 0; e < 4; e++) d[t][e] = 0.f;

#pragma unroll 5
    for (int c = 0; c < 25; c++) {
        int k0 = c * 16 + 2 * tig;
        const float* pr0 = Xb + (size_t)r0 * N0 + k0;
        const float* pr1 = Xb + (size_t)r1 * N0 + k0;
        float2 xa[4];
        xa[0] = *(const float2*)pr0;
        xa[1] = *(const float2*)pr1;
        xa[2] = *(const float2*)(pr0 + 8);
        xa[3] = *(const float2*)(pr1 + 8);
        unsigned ah[4], al[4];
#pragma unroll
        for (int e = 0; e < 4; e++) {
            ah[e] = pack_bf16x2(xa[e].x, xa[e].y);
            float f0 = __uint_as_float(ah[e] << 16);
            float f1 = __uint_as_float(ah[e] & 0xFFFF0000u);
            al[e] = pack_bf16x2(xa[e].x - f0, xa[e].y - f1);
        }
        int pb = c * 8 + tig;
#pragma unroll
        for (int t = 0; t < 7; t++) {
            int n = t * 8 + gid;
            unsigned bh0 = sBh[n * BSTR + pb];
            unsigned bh1 = sBh[n * BSTR + pb + 4];
            unsigned bl0 = sBl[n * BSTR + pb];
            unsigned bl1 = sBl[n * BSTR + pb + 4];
            mma16816(d[t], ah, bh0, bh1);
            mma16816(d[t], al, bh0, bh1);
            mma16816(d[t], ah, bl0, bl1);
        }
    }
#pragma unroll
    for (int t = 0; t < 7; t++) {
        int col = t * 8 + 2 * tig;
        *(float2*)(Yb + (size_t)r0 * NP + col) = make_float2(d[t][0], d[t][1]);
        *(float2*)(Yb + (size_t)r1 * NP + col) = make_float2(d[t][2], d[t][3]);
    }
}

// ---------------- K3: h = M^T Y (f32x2), log via HMMA Clenshaw, head ----------------
__global__ __launch_bounds__(256) void k_poly(const float* __restrict__ bl,
                                              float* __restrict__ out) {
    extern __shared__ float dsm[];
    float* sTs = dsm + OFF_TS;
    float* bufA = dsm + OFF_BA;
    float* bufB = dsm + OFF_BB;
    unsigned* sIh = (unsigned*)(dsm + OFF_IH);
    unsigned* sIl = sIh + 64 * LDI;

    __shared__ float s_row[NT];
    __shared__ float s_bb;
    __shared__ float s_red[7 * 8];

    int b = blockIdx.x;
    int tid = threadIdx.x;
    int wid = tid >> 5, lane = tid & 31;
    int gid = lane >> 2, tig = lane & 3;
    int rs = wid >> 1, ch = wid & 1;
    const float* Yb = g_Y + (size_t)b * N0 * NP;

    // ---- h = M^T Y : 125 threads, 2x10 microtile f32x2, staging in bufA/bufB ----
    {
        int rg = tid / 5, cg = tid - (tid / 5) * 5;
        int i0 = 2 * rg, j0 = 10 * cg;
        float2 h0[5] = {}, h1[5] = {};
        for (int kc = 0; kc < N0; kc += NT) {
            for (int l = tid; l < NT * NT; l += 256) {
                int r = l / NT, c = l - (l / NT) * NT;
                bufA[r * LDB + c] = g_M[(kc + r) * NP + c];
                bufB[r * LDB + c] = Yb[(kc + r) * NP + c];
            }
            __syncthreads();
            if (tid < 125) {
#pragma unroll 5
                for (int kk = 0; kk < NT; kk++) {
                    float m0 = bufA[kk * LDB + i0], m1 = bufA[kk * LDB + i0 + 1];
                    float2 a0 = make_float2(m0, m0), a1 = make_float2(m1, m1);
#pragma unroll
                    for (int j = 0; j < 5; j++) {
                        float2 yv = *(float2*)&bufB[kk * LDB + j0 + 2 * j];
                        ffma2(h0[j], a0, yv);
                        ffma2(h1[j], a1, yv);
                    }
                }
            }
            __syncthreads();
        }
        if (tid < 125) {
#pragma unroll
            for (int j = 0; j < 5; j++) {
                sTs[i0 * LDA + j0 + 2 * j] = h0[j].x;
                sTs[i0 * LDA + j0 + 2 * j + 1] = h0[j].y;
                sTs[(i0 + 1) * LDA + j0 + 2 * j] = h1[j].x;
                sTs[(i0 + 1) * LDA + j0 + 2 * j + 1] = h1[j].y;
            }
        }
        __syncthreads();
    }

    // ---- Gershgorin bound ----
    if (tid < NT) {
        float s = 0.f;
        for (int j = 0; j < NT; j++) s += fabsf(sTs[tid * LDA + j]);
        s_row[tid] = s;
    }
    __syncthreads();
    if (tid == 0) {
        float mx = 0.f;
        for (int i = 0; i < NT; i++) mx = fmaxf(mx, s_row[i]);
        s_bb = mx;
    }
    __syncthreads();
    float aa = 0.95f, bb = s_bb;
    float mid = 0.5f * (aa + bb);
    float kap = (bb - aa) / (bb + aa);
    float z = (1.f - sqrtf(fmaxf(1.f - kap * kap, 0.f))) / kap;
    float c0 = logf(mid) - logf(1.f + z * z);

    // ---- Ts = (2h - (a+b)I)/(b-a) ----
    {
        float inv = 1.f / (bb - aa);
        for (int l = tid; l < NT * NT; l += 256) {
            int i = l / NT, j = l - (l / NT) * NT;
            sTs[i * LDA + j] = (2.f * sTs[i * LDA + j] - (i == j ? (aa + bb) : 0.f)) * inv;
        }
    }
    for (int l = tid; l < NT * LDB; l += 256) {
        bufA[l] = 0.f;
        bufB[l] = 0.f;
    }
    for (int l = tid; l < 64 * LDI; l += 256) {
        sIh[l] = 0u;
        sIl[l] = 0u;
    }
    __syncthreads();
    float cD = -2.f * __powf(z, (float)CHEB_D) / (float)CHEB_D;
    if (tid < NT) bufA[tid * LDB + tid] = cD;
    __syncthreads();
    for (int t = tid; t < NT * 25; t += 256) {
        int n = t / 25, p = t - (t / 25) * 25;
        float f0 = bufA[(2 * p) * LDB + n];
        float f1 = bufA[(2 * p + 1) * LDB + n];
        unsigned h = pack_bf16x2(f0, f1);
        float q0 = __uint_as_float(h << 16), q1 = __uint_as_float(h & 0xFFFF0000u);
        sIh[n * LDI + p] = h;
        sIl[n * LDI + p] = pack_bf16x2(f0 - q0, f1 - q1);
    }
    // preload Ts A-fragments (loop-invariant), bf16 hi/lo split
    unsigned ahf[4][4], alf[4][4];
    {
        int ra0 = 16 * rs + gid, ra1 = ra0 + 8;
#pragma unroll
        for (int ks = 0; ks < 4; ks++) {
            int c0 = 16 * ks + 2 * tig;
#pragma unroll
            for (int e = 0; e < 4; e++) {
                int r = (e & 1) ? ra1 : ra0;
                int c = c0 + ((e >> 1) ? 8 : 0);
                float f0 = (r < NT && c < NT) ? sTs[r * LDA + c] : 0.f;
                float f1 = (r < NT && c + 1 < NT) ? sTs[r * LDA + c + 1] : 0.f;
                unsigned h = pack_bf16x2(f0, f1);
                float q0 = __uint_as_float(h << 16), q1 = __uint_as_float(h & 0xFFFF0000u);
                ahf[ks][e] = h;
                alf[ks][e] = pack_bf16x2(f0 - q0, f1 - q1);
            }
        }
    }
    __syncthreads();

    // ---- Clenshaw via HMMA: b_k = ck I + 2 Ts b_{k+1} - b_{k+2} ----
    float* bcur = bufA;
    float* bold = bufB;
    for (int k = CHEB_D - 1; k >= 0; k--) {
        float ck, m2;
        if (k >= 1) {
            ck = 2.f * __powf(z, (float)k) / (float)k;
            if (!(k & 1)) ck = -ck;
            m2 = 2.f;
        } else {
            ck = c0;
            m2 = 1.f;
        }
#pragma unroll
        for (int tt = 0; tt < 4; tt++) {
            float d[4] = {0.f, 0.f, 0.f, 0.f};
            int n = 32 * ch + 8 * tt + gid;
#pragma unroll
            for (int ks = 0; ks < 4; ks++) {
                unsigned b0h = sIh[n * LDI + 8 * ks + tig];
                unsigned b1h = sIh[n * LDI + 8 * ks + 4 + tig];
                unsigned b0l = sIl[n * LDI + 8 * ks + tig];
                unsigned b1l = sIl[n * LDI + 8 * ks + 4 + tig];
                mma16816(d, ahf[ks], b0h, b1h);
                mma16816(d, alf[ks], b0h, b1h);
                mma16816(d, ahf[ks], b0l, b1l);
            }
            int c0w = 32 * ch + 8 * tt + 2 * tig;
            if (c0w < NT) {
                int r = 16 * rs + gid;
                if (r < NT) {
                    float v0 = m2 * d[0] - bold[r * LDB + c0w] + (r == c0w ? ck : 0.f);
                    float v1 = m2 * d[1] - bold[r * LDB + c0w + 1] + (r == c0w + 1 ? ck : 0.f);
                    *(float2*)&bold[r * LDB + c0w] = make_float2(v0, v1);
                }
                int r2 = 16 * rs + gid + 8;
                if (r2 < NT) {
                    float v0 = m2 * d[2] - bold[r2 * LDB + c0w] + (r2 == c0w ? ck : 0.f);
                    float v1 = m2 * d[3] - bold[r2 * LDB + c0w + 1] + (r2 == c0w + 1 ? ck : 0.f);
                    *(float2*)&bold[r2 * LDB + c0w] = make_float2(v0, v1);
                }
            }
        }
        {
            float* tmp = bcur; bcur = bold; bold = tmp;
        }
        __syncthreads();
        if (k > 0) {
            for (int t = tid; t < NT * 25; t += 256) {
                int n = t / 25, p = t - (t / 25) * 25;
                float f0 = bcur[(2 * p) * LDB + n];
                float f1 = bcur[(2 * p + 1) * LDB + n];
                unsigned h = pack_bf16x2(f0, f1);
                float q0 = __uint_as_float(h << 16), q1 = __uint_as_float(h & 0xFFFF0000u);
                sIh[n * LDI + p] = h;
                sIl[n * LDI + p] = pack_bf16x2(f0 - q0, f1 - q1);
            }
            __syncthreads();
        }
    }
    float* S = bcur;

    // ---- head: out[c] = <S, Wsym_c> + bl[c] ----
    float po[7] = {0, 0, 0, 0, 0, 0, 0};
    for (int l = tid; l < NT * LDB; l += 256) {
        float s = S[l];
#pragma unroll
        for (int c = 0; c < 7; c++) po[c] += s * g_Wsym[c * (NT * LDB) + l];
    }
    int lane2 = tid & 31, warp = tid >> 5;
#pragma unroll
    for (int off = 16; off > 0; off >>= 1) {
#pragma unroll
        for (int c = 0; c < 7; c++) po[c] += __shfl_down_sync(0xffffffffu, po[c], off);
    }
    if (lane2 == 0) {
#pragma unroll
        for (int c = 0; c < 7; c++) s_red[c * 8 + warp] = po[c];
    }
    __syncthreads();
    if (tid < 7) {
        float sum = bl[tid];
#pragma unroll
        for (int w = 0; w < 8; w++) sum += s_red[tid * 8 + w];
        out[b * 7 + tid] = sum;
    }
}

extern "C" void kernel_launch(void* const* d_in, const int* in_sizes, int n_in,
                              void* d_out, int out_size) {
    const float* x  = (const float*)d_in[0];
    const float* W1 = (const float*)d_in[1];
    const float* W2 = (const float*)d_in[2];
    const float* W3 = (const float*)d_in[3];
    const float* Wl = (const float*)d_in[4];
    const float* bl = (const float*)d_in[5];
    float* out = (float*)d_out;

    static int smem_set = 0;
    if (!smem_set) {
        cudaFuncSetAttribute(k_poly, cudaFuncAttributeMaxDynamicSharedMemorySize,
                             POLY_SMEM);
        cudaFuncSetAttribute(k_xmh, cudaFuncAttributeMaxDynamicSharedMemorySize,
                             XMH_SMEM);
        smem_set = 1;
    }

    k_w2w3<<<40, 256>>>(W2, W3);
    k_w1t<<<88, 256>>>(W1);
    k_prep2<<<116, 256>>>(Wl);
    k_xmh<<<400, 512, XMH_SMEM>>>(x);
    k_poly<<<BATCH, 256, POLY_SMEM>>>(bl, out);
}